// round 8
// baseline (speedup 1.0000x reference)
#include <cuda_runtime.h>
#include <cuda_bf16.h>
#include <math.h>
#include <stdint.h>

#define B_    8
#define NH    8
#define T_    8
#define HD    32
#define C_    256
#define N_    8192
#define HW    1024
#define BHT   512            // B*NH*T
#define M_TOT 65536          // B*N

// ---------------- scratch (static device globals; no allocation) ----------------
__device__ float g_qn[(size_t)BHT * HW * HD];          //  67 MB : normalized q [bht][p][c]
__device__ float g_kn[(size_t)BHT * HD * HW];          //  67 MB : normalized shifted k [bht][c][p]
__device__ __nv_bfloat16 g_xhi[(size_t)M_TOT * C_];    //  34 MB
__device__ __nv_bfloat16 g_xlo[(size_t)M_TOT * C_];
__device__ __nv_bfloat16 g_vhi[(size_t)M_TOT * C_];
__device__ __nv_bfloat16 g_vlo[(size_t)M_TOT * C_];
__device__ __nv_bfloat16 g_ch[(size_t)BHT * HW * 64];  //  67 MB : corr hi [img][px][64]
__device__ __nv_bfloat16 g_cl[(size_t)BHT * HW * 64];  //  67 MB : corr lo
__device__ __nv_bfloat16 g_wqk_hi[512 * 256];
__device__ __nv_bfloat16 g_wqk_lo[512 * 256];
__device__ __nv_bfloat16 g_wpj_hi[256 * 256];
__device__ __nv_bfloat16 g_wpj_lo[256 * 256];
__device__ __nv_bfloat16 g_wcT_hi[32 * 64];            // w_corr -> [e][j'=dy*8+dx] padded
__device__ __nv_bfloat16 g_wcT_lo[32 * 64];

// ======================= asm helpers ==================
__device__ __forceinline__ uint32_t smem_u32(const void* p) {
    uint32_t a;
    asm("{ .reg .u64 t; cvta.to.shared.u64 t, %1; cvt.u32.u64 %0, t; }" : "=r"(a) : "l"(p));
    return a;
}
__device__ __forceinline__ void cp16(uint32_t saddr, const void* g) {
    asm volatile("cp.async.cg.shared.global [%0], [%1], 16;" :: "r"(saddr), "l"(g));
}
#define CP_COMMIT() asm volatile("cp.async.commit_group;" ::: "memory")
#define CP_WAIT1()  asm volatile("cp.async.wait_group 1;" ::: "memory")
#define CP_WAIT0()  asm volatile("cp.async.wait_group 0;" ::: "memory")

#define LDSM4(r0, r1, r2, r3, addr) \
    asm volatile("ldmatrix.sync.aligned.m8n8.x4.shared.b16 {%0,%1,%2,%3}, [%4];" \
                 : "=r"(r0), "=r"(r1), "=r"(r2), "=r"(r3) : "r"(addr))
#define MMA16816(c, a, b0, b1) \
    asm volatile("mma.sync.aligned.m16n8k16.row.col.f32.bf16.bf16.f32 " \
                 "{%0,%1,%2,%3},{%4,%5,%6,%7},{%8,%9},{%0,%1,%2,%3};" \
                 : "+f"((c)[0]), "+f"((c)[1]), "+f"((c)[2]), "+f"((c)[3]) \
                 : "r"((a)[0]), "r"((a)[1]), "r"((a)[2]), "r"((a)[3]), \
                   "r"(b0), "r"(b1))

__device__ __forceinline__ void split_bf16x2(float a, float b, uint32_t& hi, uint32_t& lo) {
    __nv_bfloat162 hb = __floats2bfloat162_rn(a, b);
    float r0 = a - __bfloat162float(__low2bfloat16(hb));
    float r1 = b - __bfloat162float(__high2bfloat16(hb));
    __nv_bfloat162 lb = __floats2bfloat162_rn(r0, r1);
    hi = *(uint32_t*)&hb;
    lo = *(uint32_t*)&lb;
}

// =================================================================================
// fp32 -> (bf16 hi, bf16 lo) split, vectorized
// =================================================================================
__global__ void __launch_bounds__(256)
conv_split(const float4* __restrict__ in, uint2* __restrict__ hi,
           uint2* __restrict__ lo, int n4)
{
    int i = blockIdx.x * 256 + threadIdx.x;
    if (i >= n4) return;
    float4 f = in[i];
    uint32_t h0, l0, h1, l1;
    split_bf16x2(f.x, f.y, h0, l0);
    split_bf16x2(f.z, f.w, h1, l1);
    hi[i] = make_uint2(h0, h1);
    lo[i] = make_uint2(l0, l1);
}

// w_corr [32 e][49 j] -> padded [32 e][64 j'] with j' = dy*8+dx
__global__ void __launch_bounds__(256)
prep_w(const float* __restrict__ wc, __nv_bfloat16* __restrict__ wh,
       __nv_bfloat16* __restrict__ wl)
{
    int i = blockIdx.x * 256 + threadIdx.x;
    if (i >= 32 * 64) return;
    int e = i >> 6, jp = i & 63;
    int dy = jp >> 3, dx = jp & 7;
    float v = (dy < 7 && dx < 7) ? wc[e * 49 + dy * 7 + dx] : 0.f;
    __nv_bfloat16 h = __float2bfloat16(v);
    float r = v - __bfloat162float(h);
    wh[i] = h;
    wl[i] = __float2bfloat16(r);
}

// =================================================================================
// Shared GEMM machinery (proven): 128x128 block, 3-stage cp.async, K=256,
// 3-term bf16 (Ahi*Bhi + Ahi*Blo + Alo*Bhi), B hi+lo in one LDSM4.
// =================================================================================
#define KGEMM 256
#define NTILES 8
#define GM_STAGE 32768
#define GM_SMEM  (3 * GM_STAGE)

__device__ __forceinline__ void stage_load(
    uint32_t sbase, const __nv_bfloat16* __restrict__ Ahi,
    const __nv_bfloat16* __restrict__ Alo, const __nv_bfloat16* __restrict__ Bhi,
    const __nv_bfloat16* __restrict__ Blo, int m0, int n0, int kt, int tid)
{
    int t = tid * 2;
    int row = t >> 2;
    int cb  = t & 3;
#pragma unroll
    for (int j = 0; j < 2; j++) {
        int c16 = cb + j;
        uint32_t soff = (uint32_t)(row * 64 + ((c16 ^ ((row >> 1) & 3)) << 4));
        size_t ga = (size_t)row * KGEMM + kt * 32 + c16 * 8;
        cp16(sbase +     0 + soff, Ahi + (size_t)m0 * KGEMM + ga);
        cp16(sbase +  8192 + soff, Alo + (size_t)m0 * KGEMM + ga);
        cp16(sbase + 16384 + soff, Bhi + (size_t)n0 * KGEMM + ga);
        cp16(sbase + 24576 + soff, Blo + (size_t)n0 * KGEMM + ga);
    }
}

__device__ __forceinline__ void gemm_mainloop(
    const __nv_bfloat16* __restrict__ Ahi, const __nv_bfloat16* __restrict__ Alo,
    const __nv_bfloat16* __restrict__ Bhi, const __nv_bfloat16* __restrict__ Blo,
    uint32_t sb, int m0, int n0, int tid, int lane, int wm, int wn,
    float acc[4][4][4])
{
#pragma unroll
    for (int i = 0; i < 4; i++)
#pragma unroll
        for (int j = 0; j < 4; j++)
#pragma unroll
            for (int q = 0; q < 4; q++) acc[i][j][q] = 0.f;

    stage_load(sb,            Ahi, Alo, Bhi, Blo, m0, n0, 0, tid);
    CP_COMMIT();
    stage_load(sb + GM_STAGE, Ahi, Alo, Bhi, Blo, m0, n0, 1, tid);
    CP_COMMIT();

    const uint32_t l2 = lane & 15;
    const uint32_t bsel = (lane & 16) ? 8192u : 0u;

    int stage = 0;
    int lstage = 2;
    for (int kt = 0; kt < NTILES; kt++) {
        CP_WAIT1();
        __syncthreads();
        if (kt + 2 < NTILES)
            stage_load(sb + lstage * GM_STAGE, Ahi, Alo, Bhi, Blo, m0, n0, kt + 2, tid);
        CP_COMMIT();
        lstage = stage;

        const uint32_t sa = sb + stage * GM_STAGE;
        stage = (stage == 2) ? 0 : stage + 1;

#pragma unroll
        for (int ks = 0; ks < 2; ks++) {
            uint32_t aaddr[4], baddr[4];
            {
                uint32_t achk = (uint32_t)(ks * 2) + (lane >> 4);
#pragma unroll
                for (int i = 0; i < 4; i++) {
                    uint32_t r = wm + l2 + i * 16;
                    aaddr[i] = sa + r * 64 + ((achk ^ ((r >> 1) & 3)) << 4);
                }
                uint32_t bchk = (uint32_t)(ks * 2) + ((l2 >> 3) & 1);
#pragma unroll
                for (int j = 0; j < 4; j++) {
                    uint32_t r = wn + (l2 & 7) + j * 8;
                    baddr[j] = sa + 16384 + r * 64 + ((bchk ^ ((r >> 1) & 3)) << 4) + bsel;
                }
            }
            uint32_t a[4][4], al[4][4], b4[4][4];
#pragma unroll
            for (int i = 0; i < 4; i++) LDSM4(a[i][0], a[i][1], a[i][2], a[i][3], aaddr[i]);
#pragma unroll
            for (int j = 0; j < 4; j++) LDSM4(b4[j][0], b4[j][1], b4[j][2], b4[j][3], baddr[j]);
#pragma unroll
            for (int i = 0; i < 4; i++) LDSM4(al[i][0], al[i][1], al[i][2], al[i][3], aaddr[i] + 8192);
#pragma unroll
            for (int i = 0; i < 4; i++)
#pragma unroll
                for (int j = 0; j < 4; j++) MMA16816(acc[i][j], a[i], b4[j][0], b4[j][1]);
#pragma unroll
            for (int i = 0; i < 4; i++)
#pragma unroll
                for (int j = 0; j < 4; j++) MMA16816(acc[i][j], a[i], b4[j][2], b4[j][3]);
#pragma unroll
            for (int i = 0; i < 4; i++)
#pragma unroll
                for (int j = 0; j < 4; j++) MMA16816(acc[i][j], al[i], b4[j][0], b4[j][1]);
        }
    }
}

// =================================================================================
// GEMM1 fused: qk GEMM + L2-normalize + temporal shift + relayout.
// =================================================================================
__global__ void __launch_bounds__(256, 2)
gemm_qk(const __nv_bfloat16* __restrict__ Ahi, const __nv_bfloat16* __restrict__ Alo,
        const __nv_bfloat16* __restrict__ Bhi, const __nv_bfloat16* __restrict__ Blo,
        float* __restrict__ qn, float* __restrict__ kn)
{
    const bool is_k = (blockIdx.x >= 2);
    const int tt_blk = (blockIdx.y >> 3) & 7;
    if (is_k && tt_blk == 0) return;        // dead k tile (shifted away)

    extern __shared__ char smg[];
    const uint32_t sb = smem_u32(smg);
    const int tid = threadIdx.x;
    const int lane = tid & 31;
    const int wid = tid >> 5;
    const int m0 = blockIdx.y * 128;
    const int n0 = blockIdx.x * 128;
    const int wm = (wid >> 2) * 64;
    const int wn = (wid & 3) * 32;

    float acc[4][4][4];
    gemm_mainloop(Ahi, Alo, Bhi, Blo, sb, m0, n0, tid, lane, wm, wn, acc);

    const int head = (((n0 & 255) + wn) >> 5);

#pragma unroll
    for (int i = 0; i < 4; i++) {
#pragma unroll
        for (int h = 0; h < 2; h++) {
            float v0[4], v1[4];
            float ss = 0.f;
#pragma unroll
            for (int j = 0; j < 4; j++) {
                v0[j] = acc[i][j][2 * h];
                v1[j] = acc[i][j][2 * h + 1];
                ss += v0[j] * v0[j] + v1[j] * v1[j];
            }
            ss += __shfl_xor_sync(0xffffffffu, ss, 1);
            ss += __shfl_xor_sync(0xffffffffu, ss, 2);
            float inv = 1.0f / fmaxf(sqrtf(ss), 1e-12f);

            int r = m0 + wm + i * 16 + (lane >> 2) + h * 8;
            int b  = r >> 13;
            int tt = (r >> 10) & 7;
            int p  = r & 1023;

            if (!is_k) {
                int bht = b * 64 + head * 8 + tt;
                float* dst = qn + ((size_t)bht * HW + p) * 32;
#pragma unroll
                for (int j = 0; j < 4; j++) {
                    int cin = j * 8 + (lane & 3) * 2;
                    *(float2*)(dst + cin) = make_float2(v0[j] * inv, v1[j] * inv);
                }
            } else {
                if (tt >= 1) {
                    int bht = b * 64 + head * 8 + (tt - 1);
                    float* dst = kn + (size_t)bht * 32 * HW + p;
#pragma unroll
                    for (int j = 0; j < 4; j++) {
                        int cin = j * 8 + (lane & 3) * 2;
                        dst[(size_t)cin * HW]       = v0[j] * inv;
                        dst[(size_t)(cin + 1) * HW] = v1[j] * inv;
                    }
                }
                if (tt == 7) {
                    int bht = b * 64 + head * 8 + 7;
                    float* dst = kn + (size_t)bht * 32 * HW + p;
#pragma unroll
                    for (int j = 0; j < 4; j++) {
                        int cin = j * 8 + (lane & 3) * 2;
                        dst[(size_t)cin * HW]       = v0[j] * inv;
                        dst[(size_t)(cin + 1) * HW] = v1[j] * inv;
                    }
                }
            }
        }
    }
}

// =================================================================================
// GEMM4: out = v @ w_proj^T + bias, fp32 out
// =================================================================================
__global__ void __launch_bounds__(256, 2)
gemm_proj(const __nv_bfloat16* __restrict__ Ahi, const __nv_bfloat16* __restrict__ Alo,
          const __nv_bfloat16* __restrict__ Bhi, const __nv_bfloat16* __restrict__ Blo,
          const float* __restrict__ bias, float* __restrict__ C, int ldc)
{
    extern __shared__ char smg[];
    const uint32_t sb = smem_u32(smg);
    const int tid = threadIdx.x;
    const int lane = tid & 31;
    const int wid = tid >> 5;
    const int m0 = blockIdx.y * 128;
    const int n0 = blockIdx.x * 128;
    const int wm = (wid >> 2) * 64;
    const int wn = (wid & 3) * 32;

    float acc[4][4][4];
    gemm_mainloop(Ahi, Alo, Bhi, Blo, sb, m0, n0, tid, lane, wm, wn, acc);

#pragma unroll
    for (int j = 0; j < 4; j++) {
        int c = n0 + wn + j * 8 + (lane & 3) * 2;
        float b0 = bias[c], b1 = bias[c + 1];
#pragma unroll
        for (int i = 0; i < 4; i++) {
            int r = m0 + wm + i * 16 + (lane >> 2);
            *(float2*)(C + (size_t)r * ldc + c) =
                make_float2(acc[i][j][0] + b0, acc[i][j][1] + b1);
            *(float2*)(C + (size_t)(r + 8) * ldc + c) =
                make_float2(acc[i][j][2] + b0, acc[i][j][3] + b1);
        }
    }
}

// =================================================================================
// corr-only with 4-channel-interleaved float4 k-tile: every tap = one LDS.128
// feeding 4 channels. dx split 4+3 keeps live accumulators small (3 CTAs/SM).
// Writes corr[img][px][64] bf16 hi/lo, j' = dy*8+dx, zeros at dx==7 / j'>=56.
// =================================================================================
#define KCOLS 38
#define KROWS 14
#define KCH4  (KROWS * KCOLS)                     // 532 float4 per cquad
#define CORR_SMEM_BYTES (8 * KCH4 * 16)           // 68096

__global__ void __launch_bounds__(256, 3)
corr_kernel(const float* __restrict__ qn, const float* __restrict__ kn,
            __nv_bfloat16* __restrict__ ch, __nv_bfloat16* __restrict__ cl)
{
    extern __shared__ float4 sh4[];
    float4* shk4 = sh4;                      // [8 cq][14 r][38 col]

    const int tid = threadIdx.x;
    const int img = blockIdx.x >> 2;
    const int yq  = (blockIdx.x & 3) * 8;

    for (int i = tid; i < 8 * KCH4; i += 256) shk4[i] = make_float4(0.f, 0.f, 0.f, 0.f);
    __syncthreads();

    // fill: kn[c][p] -> word (c&3) of float4 at [c>>2][r][3 + x]
    const float* ksrc = kn + (size_t)img * 32 * HW;
    for (int i = tid; i < 32 * 14 * 8; i += 256) {
        int c = i / 112, rem = i - (i / 112) * 112;
        int r = rem >> 3, x4 = rem & 7;
        int gy = yq - 3 + r;
        if (gy >= 0 && gy < 32) {
            float4 v = *(const float4*)(ksrc + (size_t)c * HW + gy * 32 + x4 * 4);
            float* base = (float*)(shk4 + (c >> 2) * KCH4 + r * KCOLS + 3 + x4 * 4) + (c & 3);
            base[0] = v.x; base[4] = v.y; base[8] = v.z; base[12] = v.w;
        }
    }
    __syncthreads();

    const int tx = tid & 31;
    const int ty = tid >> 5;
    const int p  = (yq + ty) * 32 + tx;

    float4 q4[8];
    {
        const float4* qv = (const float4*)(qn + ((size_t)img * HW + p) * 32);
#pragma unroll
        for (int i = 0; i < 8; i++) q4[i] = qv[i];
    }

    __nv_bfloat16* chp = ch + ((size_t)img * HW + p) * 64;
    __nv_bfloat16* clp = cl + ((size_t)img * HW + p) * 64;

#pragma unroll 1
    for (int dy = 0; dy < 7; dy++) {
        const float4* brow = shk4 + (ty + dy) * KCOLS + tx;
        float s[8];
        // dx chunk 0..3
        {
            float4 cB[4];
#pragma unroll
            for (int d = 0; d < 4; d++) cB[d] = make_float4(0.f, 0.f, 0.f, 0.f);
#pragma unroll
            for (int cq = 0; cq < 8; cq++) {
                const float4* bp = brow + cq * KCH4;
                float4 qa = q4[cq];
#pragma unroll
                for (int d = 0; d < 4; d++) {
                    float4 kv = bp[d];
                    cB[d].x += qa.x * kv.x;
                    cB[d].y += qa.y * kv.y;
                    cB[d].z += qa.z * kv.z;
                    cB[d].w += qa.w * kv.w;
                }
            }
#pragma unroll
            for (int d = 0; d < 4; d++) s[d] = (cB[d].x + cB[d].y) + (cB[d].z + cB[d].w);
        }
        // dx chunk 4..6
        {
            float4 cB[3];
#pragma unroll
            for (int d = 0; d < 3; d++) cB[d] = make_float4(0.f, 0.f, 0.f, 0.f);
#pragma unroll
            for (int cq = 0; cq < 8; cq++) {
                const float4* bp = brow + cq * KCH4 + 4;
                float4 qa = q4[cq];
#pragma unroll
                for (int d = 0; d < 3; d++) {
                    float4 kv = bp[d];
                    cB[d].x += qa.x * kv.x;
                    cB[d].y += qa.y * kv.y;
                    cB[d].z += qa.z * kv.z;
                    cB[d].w += qa.w * kv.w;
                }
            }
#pragma unroll
            for (int d = 0; d < 3; d++) s[4 + d] = (cB[d].x + cB[d].y) + (cB[d].z + cB[d].w);
        }
        s[7] = 0.f;
        uint32_t h4[4], l4[4];
#pragma unroll
        for (int q = 0; q < 4; q++) split_bf16x2(s[2 * q], s[2 * q + 1], h4[q], l4[q]);
        *(uint4*)(chp + dy * 8) = make_uint4(h4[0], h4[1], h4[2], h4[3]);
        *(uint4*)(clp + dy * 8) = make_uint4(l4[0], l4[1], l4[2], l4[3]);
    }
    uint4 z = make_uint4(0, 0, 0, 0);
    *(uint4*)(chp + 56) = z;
    *(uint4*)(clp + 56) = z;
}

// =================================================================================
// proj_mma: v[px, e] = corr[px, 0..63] @ wcT[e, 0..63] + b_corr[e], 3-term bf16.
// =================================================================================
#define PJ_A_HI 0
#define PJ_A_LO 32768
#define PJ_W_HI 65536
#define PJ_W_LO (65536 + 4096)
#define PJ_SMEM (65536 + 8192)

__global__ void __launch_bounds__(256)
proj_mma(const __nv_bfloat16* __restrict__ ch, const __nv_bfloat16* __restrict__ cl,
         const __nv_bfloat16* __restrict__ wh, const __nv_bfloat16* __restrict__ wl,
         const float* __restrict__ bc,
         __nv_bfloat16* __restrict__ vhi, __nv_bfloat16* __restrict__ vlo)
{
    extern __shared__ char smp[];
    const uint32_t sb = smem_u32(smp);
    const int tid = threadIdx.x;
    const int lane = tid & 31;
    const int wid = tid >> 5;
    const int img = blockIdx.x >> 2;
    const int px0 = (blockIdx.x & 3) * 256;

    for (int i = tid; i < 2048; i += 256) {
        int px = i >> 3, chk = i & 7;
        uint32_t sw = (uint32_t)(px * 128 + ((chk ^ (px & 7)) << 4));
        size_t gofs = ((size_t)img * HW + px0 + px) * 64 + chk * 8;
        cp16(sb + PJ_A_HI + sw, ch + gofs);
        cp16(sb + PJ_A_LO + sw, cl + gofs);
    }
    if (tid < 256) {
        int r = tid >> 3, chk = tid & 7;
        uint32_t sw = (uint32_t)(r * 128 + ((chk ^ (r & 7)) << 4));
        cp16(sb + PJ_W_HI + sw, wh + r * 64 + chk * 8);
        cp16(sb + PJ_W_LO + sw, wl + r * 64 + chk * 8);
    }
    CP_COMMIT();
    CP_WAIT0();
    __syncthreads();

    const int wm = wid * 32;
    float acc[2][4][4];
#pragma unroll
    for (int m = 0; m < 2; m++)
#pragma unroll
        for (int n = 0; n < 4; n++)
#pragma unroll
            for (int q = 0; q < 4; q++) acc[m][n][q] = 0.f;

    const int lq = lane >> 2;
    const int lr = lane & 3;

#pragma unroll
    for (int k = 0; k < 4; k++) {
        uint32_t bh[4][2], bl[4][2];
#pragma unroll
        for (int n = 0; n < 4; n++) {
            uint32_t row = n * 8 + lq;
            uint32_t o0 = row * 128 + (((2 * k)     ^ (row & 7)) << 4) + lr * 4;
            uint32_t o1 = row * 128 + (((2 * k + 1) ^ (row & 7)) << 4) + lr * 4;
            bh[n][0] = *(const uint32_t*)(smp + PJ_W_HI + o0);
            bh[n][1] = *(const uint32_t*)(smp + PJ_W_HI + o1);
            bl[n][0] = *(const uint32_t*)(smp + PJ_W_LO + o0);
            bl[n][1] = *(const uint32_t*)(smp + PJ_W_LO + o1);
        }
#pragma unroll
        for (int m = 0; m < 2; m++) {
            uint32_t r0 = wm + m * 16 + lq;
            uint32_t r1 = r0 + 8;
            uint32_t a00 = r0 * 128 + (((2 * k)     ^ (r0 & 7)) << 4) + lr * 4;
            uint32_t a10 = r1 * 128 + (((2 * k)     ^ (r1 & 7)) << 4) + lr * 4;
            uint32_t a01 = r0 * 128 + (((2 * k + 1) ^ (r0 & 7)) << 4) + lr * 4;
            uint32_t a11 = r1 * 128 + (((2 * k + 1) ^ (r1 & 7)) << 4) + lr * 4;
            uint32_t Ah[4], Al[4];
            Ah[0] = *(const uint32_t*)(smp + PJ_A_HI + a00);
            Ah[1] = *(const uint32_t*)(smp + PJ_A_HI + a10);
            Ah[2] = *(const uint32_t*)(smp + PJ_A_HI + a01);
            Ah[3] = *(const uint32_t*)(smp + PJ_A_HI + a11);
            Al[0] = *(const uint32_t*)(smp + PJ_A_LO + a00);
            Al[1] = *(const uint32_t*)(smp + PJ_A_LO + a10);
            Al[2] = *(const uint32_t*)(smp + PJ_A_LO + a01);
            Al[3] = *(const uint32_t*)(smp + PJ_A_LO + a11);
#pragma unroll
            for (int n = 0; n < 4; n++) {
                MMA16816(acc[m][n], Ah, bh[n][0], bh[n][1]);
                MMA16816(acc[m][n], Al, bh[n][0], bh[n][1]);
                MMA16816(acc[m][n], Ah, bl[n][0], bl[n][1]);
            }
        }
    }

    const int b    = img >> 6;
    const int head = (img >> 3) & 7;
    const int t    = img & 7;
#pragma unroll
    for (int n = 0; n < 4; n++) {
        int col = n * 8 + lr * 2;
        float b0 = bc[col], b1 = bc[col + 1];
#pragma unroll
        for (int m = 0; m < 2; m++) {
            int px = px0 + wm + m * 16 + lq;
            size_t row0 = (size_t)b * N_ + t * HW + px;
            size_t row1 = row0 + 8;
            size_t g0 = row0 * C_ + head * 32 + col;
            size_t g1 = row1 * C_ + head * 32 + col;
            uint32_t h0, l0, h1, l1;
            split_bf16x2(acc[m][n][0] + b0, acc[m][n][1] + b1, h0, l0);
            split_bf16x2(acc[m][n][2] + b0, acc[m][n][3] + b1, h1, l1);
            *(uint32_t*)(vhi + g0) = h0;
            *(uint32_t*)(vlo + g0) = l0;
            *(uint32_t*)(vhi + g1) = h1;
            *(uint32_t*)(vlo + g1) = l1;
        }
    }
}

// =================================================================================
extern "C" void kernel_launch(void* const* d_in, const int* in_sizes, int n_in,
                              void* d_out, int out_size)
{
    const float* x      = (const float*)d_in[0];
    const float* w_qk   = (const float*)d_in[1];
    const float* w_corr = (const float*)d_in[2];
    const float* b_corr = (const float*)d_in[3];
    const float* w_proj = (const float*)d_in[4];
    const float* b_proj = (const float*)d_in[5];
    float* out = (float*)d_out;

    float *qn, *kn;
    __nv_bfloat16 *xhi, *xlo, *vhi, *vlo, *wqh, *wql, *wph, *wpl, *chp, *clp, *wch, *wcl;
    cudaGetSymbolAddress((void**)&qn,  g_qn);
    cudaGetSymbolAddress((void**)&kn,  g_kn);
    cudaGetSymbolAddress((void**)&xhi, g_xhi);
    cudaGetSymbolAddress((void**)&xlo, g_xlo);
    cudaGetSymbolAddress((void**)&vhi, g_vhi);
    cudaGetSymbolAddress((void**)&vlo, g_vlo);
    cudaGetSymbolAddress((void**)&wqh, g_wqk_hi);
    cudaGetSymbolAddress((void**)&wql, g_wqk_lo);
    cudaGetSymbolAddress((void**)&wph, g_wpj_hi);
    cudaGetSymbolAddress((void**)&wpl, g_wpj_lo);
    cudaGetSymbolAddress((void**)&chp, g_ch);
    cudaGetSymbolAddress((void**)&clp, g_cl);
    cudaGetSymbolAddress((void**)&wch, g_wcT_hi);
    cudaGetSymbolAddress((void**)&wcl, g_wcT_lo);

    cudaFuncSetAttribute(gemm_qk,   cudaFuncAttributeMaxDynamicSharedMemorySize, GM_SMEM);
    cudaFuncSetAttribute(gemm_proj, cudaFuncAttributeMaxDynamicSharedMemorySize, GM_SMEM);
    cudaFuncSetAttribute(corr_kernel, cudaFuncAttributeMaxDynamicSharedMemorySize,
                         CORR_SMEM_BYTES);
    cudaFuncSetAttribute(proj_mma, cudaFuncAttributeMaxDynamicSharedMemorySize, PJ_SMEM);

    // 0) hi/lo splits + w_corr prep
    conv_split<<<(M_TOT * C_ / 4 + 255) / 256, 256>>>((const float4*)x, (uint2*)xhi, (uint2*)xlo, M_TOT * C_ / 4);
    conv_split<<<(512 * 256 / 4 + 255) / 256, 256>>>((const float4*)w_qk, (uint2*)wqh, (uint2*)wql, 512 * 256 / 4);
    conv_split<<<(256 * 256 / 4 + 255) / 256, 256>>>((const float4*)w_proj, (uint2*)wph, (uint2*)wpl, 256 * 256 / 4);
    prep_w<<<8, 256>>>(w_corr, wch, wcl);

    // 1) qk GEMM fused with normalize + temporal shift + relayout
    gemm_qk<<<dim3(4, 512), 256, GM_SMEM>>>(xhi, xlo, wqh, wql, qn, kn);

    // 2) 7x7 correlation -> corr bf16 hi/lo (float4 taps)
    corr_kernel<<<BHT * 4, 256, CORR_SMEM_BYTES>>>(qn, kn, chp, clp);

    // 3) projection (49->32) via mma -> v bf16 hi/lo
    proj_mma<<<BHT * 4, 256, PJ_SMEM>>>(chp, clp, wch, wcl, b_corr, vhi, vlo);

    // 4) out = v @ w_proj^T + b_proj
    gemm_proj<<<dim3(2, 512), 256, GM_SMEM>>>(vhi, vlo, wph, wpl, b_proj, out, 256);
}

// round 9
// speedup vs baseline: 1.0946x; 1.0946x over previous
#include <cuda_runtime.h>
#include <cuda_bf16.h>
#include <math.h>
#include <stdint.h>

#define B_    8
#define NH    8
#define T_    8
#define HD    32
#define C_    256
#define N_    8192
#define HW    1024
#define BHT   512            // B*NH*T
#define M_TOT 65536          // B*N

// ---------------- scratch (static device globals; no allocation) ----------------
__device__ __nv_bfloat16 g_qh[(size_t)BHT * HW * 32];  // q hi [img][px][ch]
__device__ __nv_bfloat16 g_ql[(size_t)BHT * HW * 32];
__device__ __nv_bfloat16 g_kh[(size_t)BHT * HW * 32];  // k hi (shifted) [img][px][ch]
__device__ __nv_bfloat16 g_kl[(size_t)BHT * HW * 32];
__device__ __nv_bfloat16 g_xhi[(size_t)M_TOT * C_];
__device__ __nv_bfloat16 g_xlo[(size_t)M_TOT * C_];
__device__ __nv_bfloat16 g_vhi[(size_t)M_TOT * C_];
__device__ __nv_bfloat16 g_vlo[(size_t)M_TOT * C_];
__device__ __nv_bfloat16 g_ch[(size_t)BHT * HW * 64];  // corr hi [img][px][64]
__device__ __nv_bfloat16 g_cl[(size_t)BHT * HW * 64];
__device__ __nv_bfloat16 g_wqk_hi[512 * 256];
__device__ __nv_bfloat16 g_wqk_lo[512 * 256];
__device__ __nv_bfloat16 g_wpj_hi[256 * 256];
__device__ __nv_bfloat16 g_wpj_lo[256 * 256];
__device__ __nv_bfloat16 g_wcT_hi[32 * 64];
__device__ __nv_bfloat16 g_wcT_lo[32 * 64];

// ======================= asm helpers ==================
__device__ __forceinline__ uint32_t smem_u32(const void* p) {
    uint32_t a;
    asm("{ .reg .u64 t; cvta.to.shared.u64 t, %1; cvt.u32.u64 %0, t; }" : "=r"(a) : "l"(p));
    return a;
}
__device__ __forceinline__ void cp16(uint32_t saddr, const void* g) {
    asm volatile("cp.async.cg.shared.global [%0], [%1], 16;" :: "r"(saddr), "l"(g));
}
#define CP_COMMIT() asm volatile("cp.async.commit_group;" ::: "memory")
#define CP_WAIT1()  asm volatile("cp.async.wait_group 1;" ::: "memory")
#define CP_WAIT0()  asm volatile("cp.async.wait_group 0;" ::: "memory")

#define LDSM4(r0, r1, r2, r3, addr) \
    asm volatile("ldmatrix.sync.aligned.m8n8.x4.shared.b16 {%0,%1,%2,%3}, [%4];" \
                 : "=r"(r0), "=r"(r1), "=r"(r2), "=r"(r3) : "r"(addr))
#define MMA16816(c, a0, a1, a2, a3, b0, b1) \
    asm volatile("mma.sync.aligned.m16n8k16.row.col.f32.bf16.bf16.f32 " \
                 "{%0,%1,%2,%3},{%4,%5,%6,%7},{%8,%9},{%0,%1,%2,%3};" \
                 : "+f"((c)[0]), "+f"((c)[1]), "+f"((c)[2]), "+f"((c)[3]) \
                 : "r"(a0), "r"(a1), "r"(a2), "r"(a3), "r"(b0), "r"(b1))

__device__ __forceinline__ void split_bf16x2(float a, float b, uint32_t& hi, uint32_t& lo) {
    __nv_bfloat162 hb = __floats2bfloat162_rn(a, b);
    float r0 = a - __bfloat162float(__low2bfloat16(hb));
    float r1 = b - __bfloat162float(__high2bfloat16(hb));
    __nv_bfloat162 lb = __floats2bfloat162_rn(r0, r1);
    hi = *(uint32_t*)&hb;
    lo = *(uint32_t*)&lb;
}

// =================================================================================
__global__ void __launch_bounds__(256)
conv_split(const float4* __restrict__ in, uint2* __restrict__ hi,
           uint2* __restrict__ lo, int n4)
{
    int i = blockIdx.x * 256 + threadIdx.x;
    if (i >= n4) return;
    float4 f = in[i];
    uint32_t h0, l0, h1, l1;
    split_bf16x2(f.x, f.y, h0, l0);
    split_bf16x2(f.z, f.w, h1, l1);
    hi[i] = make_uint2(h0, h1);
    lo[i] = make_uint2(l0, l1);
}

// w_corr [32 e][49 j] -> padded [32 e][64 j'] with j' = dy*8+dx
__global__ void __launch_bounds__(256)
prep_w(const float* __restrict__ wc, __nv_bfloat16* __restrict__ wh,
       __nv_bfloat16* __restrict__ wl)
{
    int i = blockIdx.x * 256 + threadIdx.x;
    if (i >= 32 * 64) return;
    int e = i >> 6, jp = i & 63;
    int dy = jp >> 3, dx = jp & 7;
    float v = (dy < 7 && dx < 7) ? wc[e * 49 + dy * 7 + dx] : 0.f;
    __nv_bfloat16 h = __float2bfloat16(v);
    float r = v - __bfloat162float(h);
    wh[i] = h;
    wl[i] = __float2bfloat16(r);
}

// =================================================================================
// Shared GEMM machinery (proven): 128x128 block, 3-stage cp.async, K=256, 3-term.
// =================================================================================
#define KGEMM 256
#define NTILES 8
#define GM_STAGE 32768
#define GM_SMEM  (3 * GM_STAGE)

__device__ __forceinline__ void stage_load(
    uint32_t sbase, const __nv_bfloat16* __restrict__ Ahi,
    const __nv_bfloat16* __restrict__ Alo, const __nv_bfloat16* __restrict__ Bhi,
    const __nv_bfloat16* __restrict__ Blo, int m0, int n0, int kt, int tid)
{
    int t = tid * 2;
    int row = t >> 2;
    int cb  = t & 3;
#pragma unroll
    for (int j = 0; j < 2; j++) {
        int c16 = cb + j;
        uint32_t soff = (uint32_t)(row * 64 + ((c16 ^ ((row >> 1) & 3)) << 4));
        size_t ga = (size_t)row * KGEMM + kt * 32 + c16 * 8;
        cp16(sbase +     0 + soff, Ahi + (size_t)m0 * KGEMM + ga);
        cp16(sbase +  8192 + soff, Alo + (size_t)m0 * KGEMM + ga);
        cp16(sbase + 16384 + soff, Bhi + (size_t)n0 * KGEMM + ga);
        cp16(sbase + 24576 + soff, Blo + (size_t)n0 * KGEMM + ga);
    }
}

__device__ __forceinline__ void gemm_mainloop(
    const __nv_bfloat16* __restrict__ Ahi, const __nv_bfloat16* __restrict__ Alo,
    const __nv_bfloat16* __restrict__ Bhi, const __nv_bfloat16* __restrict__ Blo,
    uint32_t sb, int m0, int n0, int tid, int lane, int wm, int wn,
    float acc[4][4][4])
{
#pragma unroll
    for (int i = 0; i < 4; i++)
#pragma unroll
        for (int j = 0; j < 4; j++)
#pragma unroll
            for (int q = 0; q < 4; q++) acc[i][j][q] = 0.f;

    stage_load(sb,            Ahi, Alo, Bhi, Blo, m0, n0, 0, tid);
    CP_COMMIT();
    stage_load(sb + GM_STAGE, Ahi, Alo, Bhi, Blo, m0, n0, 1, tid);
    CP_COMMIT();

    const uint32_t l2 = lane & 15;
    const uint32_t bsel = (lane & 16) ? 8192u : 0u;

    int stage = 0;
    int lstage = 2;
    for (int kt = 0; kt < NTILES; kt++) {
        CP_WAIT1();
        __syncthreads();
        if (kt + 2 < NTILES)
            stage_load(sb + lstage * GM_STAGE, Ahi, Alo, Bhi, Blo, m0, n0, kt + 2, tid);
        CP_COMMIT();
        lstage = stage;

        const uint32_t sa = sb + stage * GM_STAGE;
        stage = (stage == 2) ? 0 : stage + 1;

#pragma unroll
        for (int ks = 0; ks < 2; ks++) {
            uint32_t aaddr[4], baddr[4];
            {
                uint32_t achk = (uint32_t)(ks * 2) + (lane >> 4);
#pragma unroll
                for (int i = 0; i < 4; i++) {
                    uint32_t r = wm + l2 + i * 16;
                    aaddr[i] = sa + r * 64 + ((achk ^ ((r >> 1) & 3)) << 4);
                }
                uint32_t bchk = (uint32_t)(ks * 2) + ((l2 >> 3) & 1);
#pragma unroll
                for (int j = 0; j < 4; j++) {
                    uint32_t r = wn + (l2 & 7) + j * 8;
                    baddr[j] = sa + 16384 + r * 64 + ((bchk ^ ((r >> 1) & 3)) << 4) + bsel;
                }
            }
            uint32_t a[4][4], al[4][4], b4[4][4];
#pragma unroll
            for (int i = 0; i < 4; i++) LDSM4(a[i][0], a[i][1], a[i][2], a[i][3], aaddr[i]);
#pragma unroll
            for (int j = 0; j < 4; j++) LDSM4(b4[j][0], b4[j][1], b4[j][2], b4[j][3], baddr[j]);
#pragma unroll
            for (int i = 0; i < 4; i++) LDSM4(al[i][0], al[i][1], al[i][2], al[i][3], aaddr[i] + 8192);
#pragma unroll
            for (int i = 0; i < 4; i++)
#pragma unroll
                for (int j = 0; j < 4; j++)
                    MMA16816(acc[i][j], a[i][0], a[i][1], a[i][2], a[i][3], b4[j][0], b4[j][1]);
#pragma unroll
            for (int i = 0; i < 4; i++)
#pragma unroll
                for (int j = 0; j < 4; j++)
                    MMA16816(acc[i][j], a[i][0], a[i][1], a[i][2], a[i][3], b4[j][2], b4[j][3]);
#pragma unroll
            for (int i = 0; i < 4; i++)
#pragma unroll
                for (int j = 0; j < 4; j++)
                    MMA16816(acc[i][j], al[i][0], al[i][1], al[i][2], al[i][3], b4[j][0], b4[j][1]);
        }
    }
}

// =================================================================================
// GEMM1 fused: qk GEMM + L2-normalize + temporal shift; emits q AND k as
// bf16 hi/lo in identical [img][px][ch] layout.
// =================================================================================
__global__ void __launch_bounds__(256, 2)
gemm_qk(const __nv_bfloat16* __restrict__ Ahi, const __nv_bfloat16* __restrict__ Alo,
        const __nv_bfloat16* __restrict__ Bhi, const __nv_bfloat16* __restrict__ Blo,
        __nv_bfloat16* __restrict__ qh, __nv_bfloat16* __restrict__ ql,
        __nv_bfloat16* __restrict__ kh, __nv_bfloat16* __restrict__ kl)
{
    const bool is_k = (blockIdx.x >= 2);
    const int tt_blk = (blockIdx.y >> 3) & 7;
    if (is_k && tt_blk == 0) return;        // dead k tile (shifted away)

    extern __shared__ char smg[];
    const uint32_t sb = smem_u32(smg);
    const int tid = threadIdx.x;
    const int lane = tid & 31;
    const int wid = tid >> 5;
    const int m0 = blockIdx.y * 128;
    const int n0 = blockIdx.x * 128;
    const int wm = (wid >> 2) * 64;
    const int wn = (wid & 3) * 32;

    float acc[4][4][4];
    gemm_mainloop(Ahi, Alo, Bhi, Blo, sb, m0, n0, tid, lane, wm, wn, acc);

    const int head = (((n0 & 255) + wn) >> 5);

#pragma unroll
    for (int i = 0; i < 4; i++) {
#pragma unroll
        for (int h = 0; h < 2; h++) {
            float v0[4], v1[4];
            float ss = 0.f;
#pragma unroll
            for (int j = 0; j < 4; j++) {
                v0[j] = acc[i][j][2 * h];
                v1[j] = acc[i][j][2 * h + 1];
                ss += v0[j] * v0[j] + v1[j] * v1[j];
            }
            ss += __shfl_xor_sync(0xffffffffu, ss, 1);
            ss += __shfl_xor_sync(0xffffffffu, ss, 2);
            float inv = 1.0f / fmaxf(sqrtf(ss), 1e-12f);

            int r = m0 + wm + i * 16 + (lane >> 2) + h * 8;
            int b  = r >> 13;
            int tt = (r >> 10) & 7;
            int p  = r & 1023;

            uint32_t hw[4], lw[4];
#pragma unroll
            for (int j = 0; j < 4; j++)
                split_bf16x2(v0[j] * inv, v1[j] * inv, hw[j], lw[j]);

            if (!is_k) {
                size_t base = ((size_t)(b * 64 + head * 8 + tt) * HW + p) * 32;
#pragma unroll
                for (int j = 0; j < 4; j++) {
                    int col = j * 8 + (lane & 3) * 2;
                    *(uint32_t*)(qh + base + col) = hw[j];
                    *(uint32_t*)(ql + base + col) = lw[j];
                }
            } else {
                if (tt >= 1) {
                    size_t base = ((size_t)(b * 64 + head * 8 + (tt - 1)) * HW + p) * 32;
#pragma unroll
                    for (int j = 0; j < 4; j++) {
                        int col = j * 8 + (lane & 3) * 2;
                        *(uint32_t*)(kh + base + col) = hw[j];
                        *(uint32_t*)(kl + base + col) = lw[j];
                    }
                }
                if (tt == 7) {
                    size_t base = ((size_t)(b * 64 + head * 8 + 7) * HW + p) * 32;
#pragma unroll
                    for (int j = 0; j < 4; j++) {
                        int col = j * 8 + (lane & 3) * 2;
                        *(uint32_t*)(kh + base + col) = hw[j];
                        *(uint32_t*)(kl + base + col) = lw[j];
                    }
                }
            }
        }
    }
}

// =================================================================================
// GEMM4: out = v @ w_proj^T + bias, fp32 out
// =================================================================================
__global__ void __launch_bounds__(256, 2)
gemm_proj(const __nv_bfloat16* __restrict__ Ahi, const __nv_bfloat16* __restrict__ Alo,
          const __nv_bfloat16* __restrict__ Bhi, const __nv_bfloat16* __restrict__ Blo,
          const float* __restrict__ bias, float* __restrict__ C, int ldc)
{
    extern __shared__ char smg[];
    const uint32_t sb = smem_u32(smg);
    const int tid = threadIdx.x;
    const int lane = tid & 31;
    const int wid = tid >> 5;
    const int m0 = blockIdx.y * 128;
    const int n0 = blockIdx.x * 128;
    const int wm = (wid >> 2) * 64;
    const int wn = (wid & 3) * 32;

    float acc[4][4][4];
    gemm_mainloop(Ahi, Alo, Bhi, Blo, sb, m0, n0, tid, lane, wm, wn, acc);

#pragma unroll
    for (int j = 0; j < 4; j++) {
        int c = n0 + wn + j * 8 + (lane & 3) * 2;
        float b0 = bias[c], b1 = bias[c + 1];
#pragma unroll
        for (int i = 0; i < 4; i++) {
            int r = m0 + wm + i * 16 + (lane >> 2);
            *(float2*)(C + (size_t)r * ldc + c) =
                make_float2(acc[i][j][0] + b0, acc[i][j][1] + b1);
            *(float2*)(C + (size_t)(r + 8) * ldc + c) =
                make_float2(acc[i][j][2] + b0, acc[i][j][3] + b1);
        }
    }
}

// =================================================================================
// corr_mma: banded tensor-core 7x7 correlation.
// Block = quarter image (8 y-rows), 512 thr (16 warps), warp = one 16-px segment.
// A = q[16px][32ch], B = k row [24 px][32ch] (zero-padded), 3-term bf16 mma.
// Band extracted via per-warp smem buffer -> g_ch/g_cl [img][px][64].
// smem: q hi 0 /lo 16384 (16KB each); k hi 32768 /lo 68608 (35840 each,
// rows = 14 y x 40 px, 64B/row, swizzled); sbuf 104448 + w*1664. Total 131072.
// =================================================================================
#define CM_KH 32768
#define CM_KL 68608
#define CM_SB 104448
#define CM_SMEM 131072

__global__ void __launch_bounds__(512)
corr_mma(const __nv_bfloat16* __restrict__ qh, const __nv_bfloat16* __restrict__ ql,
         const __nv_bfloat16* __restrict__ kh, const __nv_bfloat16* __restrict__ kl,
         __nv_bfloat16* __restrict__ ch, __nv_bfloat16* __restrict__ cl)
{
    extern __shared__ char sm[];
    const uint32_t sb = smem_u32(sm);
    const int tid  = threadIdx.x;
    const int lane = tid & 31;
    const int w    = tid >> 5;           // warp = segment 0..15
    const int img  = blockIdx.x >> 2;
    const int yq   = (blockIdx.x & 3) * 8;

    // zero whole k region (both hi+lo: 71680 B = 4480 uint4)
    for (int i = tid; i < 4480; i += 512)
        ((uint4*)(sm + CM_KH))[i] = make_uint4(0, 0, 0, 0);
    __syncthreads();

    // q fill: 256 px x 4 chunks x {hi,lo} = 2048 cp16
    for (int i = tid; i < 2048; i += 512) {
        int hl = i >> 10;
        int px = (i >> 2) & 255;
        int c  = i & 3;
        const __nv_bfloat16* src = (hl ? ql : qh) +
            ((size_t)img * HW + yq * 32 + px) * 32 + c * 8;
        uint32_t dst = sb + hl * 16384 + px * 64 + ((c ^ ((px >> 1) & 3)) << 4);
        cp16(dst, src);
    }
    // k fill: 14 rows x 32 px x 4 chunks x {hi,lo} = 3584 cp16 (valid rows only)
    for (int i = tid; i < 3584; i += 512) {
        int hl = i & 1;
        int j  = i >> 1;              // 0..1791
        int row = j >> 7;             // 0..13
        int r2  = j & 127;
        int px  = r2 >> 2;            // 0..31
        int c   = r2 & 3;
        int y = yq - 3 + row;
        if (y >= 0 && y < 32) {
            int rlin = row * 40 + px + 3;
            uint32_t dst = sb + CM_KH + hl * 35840 + rlin * 64 +
                           ((c ^ ((rlin >> 1) & 3)) << 4);
            const __nv_bfloat16* src = (hl ? kl : kh) +
                ((size_t)img * HW + y * 32 + px) * 32 + c * 8;
            cp16(dst, src);
        }
    }
    CP_COMMIT();
    CP_WAIT0();
    __syncthreads();

    const int yloc = w >> 1;
    const int x0   = (w & 1) * 16;

    // A fragments (reused across all dy): 2 k16 chunks, hi+lo
    uint32_t Ah[2][4], Al[2][4];
#pragma unroll
    for (int f = 0; f < 2; f++) {
        uint32_t r = w * 16 + (lane & 15);
        uint32_t c = f * 2 + (lane >> 4);
        uint32_t addr = sb + r * 64 + ((c ^ ((r >> 1) & 3)) << 4);
        LDSM4(Ah[f][0], Ah[f][1], Ah[f][2], Ah[f][3], addr);
        LDSM4(Al[f][0], Al[f][1], Al[f][2], Al[f][3], addr + 16384);
    }

    float* sbuf = (float*)(sm + CM_SB + w * 1664);   // [16][26]
    const int lq = lane >> 2, lr = lane & 3;
    const int rr = lane >> 1;                        // band row 0..15
    const int odd = lane & 1;
    const size_t pxg = (size_t)img * HW + yq * 32 + w * 16 + rr;
    __nv_bfloat16* chp = ch + pxg * 64;
    __nv_bfloat16* clp = cl + pxg * 64;

#pragma unroll 1
    for (int dy = 0; dy < 7; dy++) {
        // B fragments: 3 n8 tiles x k32, hi+lo
        const int row = yloc + dy;
        uint32_t Bh[3][4], Bl[3][4];
#pragma unroll
        for (int nt = 0; nt < 3; nt++) {
            uint32_t rlin = row * 40 + x0 + nt * 8 + (lane & 7);
            uint32_t c = lane >> 3;
            uint32_t addr = sb + CM_KH + rlin * 64 + ((c ^ ((rlin >> 1) & 3)) << 4);
            LDSM4(Bh[nt][0], Bh[nt][1], Bh[nt][2], Bh[nt][3], addr);
            LDSM4(Bl[nt][0], Bl[nt][1], Bl[nt][2], Bl[nt][3], addr + 35840);
        }
        float acc[3][4];
#pragma unroll
        for (int nt = 0; nt < 3; nt++)
#pragma unroll
            for (int q = 0; q < 4; q++) acc[nt][q] = 0.f;

#pragma unroll
        for (int nt = 0; nt < 3; nt++) {
            MMA16816(acc[nt], Ah[0][0], Ah[0][1], Ah[0][2], Ah[0][3], Bh[nt][0], Bh[nt][1]);
            MMA16816(acc[nt], Ah[1][0], Ah[1][1], Ah[1][2], Ah[1][3], Bh[nt][2], Bh[nt][3]);
            MMA16816(acc[nt], Ah[0][0], Ah[0][1], Ah[0][2], Ah[0][3], Bl[nt][0], Bl[nt][1]);
            MMA16816(acc[nt], Ah[1][0], Ah[1][1], Ah[1][2], Ah[1][3], Bl[nt][2], Bl[nt][3]);
            MMA16816(acc[nt], Al[0][0], Al[0][1], Al[0][2], Al[0][3], Bh[nt][0], Bh[nt][1]);
            MMA16816(acc[nt], Al[1][0], Al[1][1], Al[1][2], Al[1][3], Bh[nt][2], Bh[nt][3]);
        }

        // stage accums to per-warp smem buffer
        __syncwarp();
#pragma unroll
        for (int nt = 0; nt < 3; nt++) {
            *(float2*)&sbuf[lq * 26 + nt * 8 + lr * 2]       = make_float2(acc[nt][0], acc[nt][1]);
            *(float2*)&sbuf[(lq + 8) * 26 + nt * 8 + lr * 2] = make_float2(acc[nt][2], acc[nt][3]);
        }
        __syncwarp();

        // band read: row rr needs cols rr..rr+6 (dx = col - rr)
        if (!odd) {
            float s0 = sbuf[27 * rr + 0], s1 = sbuf[27 * rr + 1];
            float s2 = sbuf[27 * rr + 2], s3 = sbuf[27 * rr + 3];
            uint32_t h0, l0, h1, l1;
            split_bf16x2(s0, s1, h0, l0);
            split_bf16x2(s2, s3, h1, l1);
            *(uint2*)(chp + dy * 8) = make_uint2(h0, h1);
            *(uint2*)(clp + dy * 8) = make_uint2(l0, l1);
        } else {
            float s4 = sbuf[27 * rr + 4], s5 = sbuf[27 * rr + 5];
            float s6 = sbuf[27 * rr + 6];
            uint32_t h0, l0, h1, l1;
            split_bf16x2(s4, s5, h0, l0);
            split_bf16x2(s6, 0.f, h1, l1);
            *(uint2*)(chp + dy * 8 + 4) = make_uint2(h0, h1);
            *(uint2*)(clp + dy * 8 + 4) = make_uint2(l0, l1);
        }
        __syncwarp();
    }

    // zero tail j' = 56..63
    {
        uint2 z = make_uint2(0, 0);
        *(uint2*)(chp + 56 + odd * 4) = z;
        *(uint2*)(clp + 56 + odd * 4) = z;
    }
}

// =================================================================================
// proj_mma: v[px, e] = corr[px, 0..63] @ wcT[e, 0..63] + b_corr[e], 3-term bf16.
// =================================================================================
#define PJ_A_HI 0
#define PJ_A_LO 32768
#define PJ_W_HI 65536
#define PJ_W_LO (65536 + 4096)
#define PJ_SMEM (65536 + 8192)

__global__ void __launch_bounds__(256)
proj_mma(const __nv_bfloat16* __restrict__ ch, const __nv_bfloat16* __restrict__ cl,
         const __nv_bfloat16* __restrict__ wh, const __nv_bfloat16* __restrict__ wl,
         const float* __restrict__ bc,
         __nv_bfloat16* __restrict__ vhi, __nv_bfloat16* __restrict__ vlo)
{
    extern __shared__ char smp[];
    const uint32_t sb = smem_u32(smp);
    const int tid = threadIdx.x;
    const int lane = tid & 31;
    const int wid = tid >> 5;
    const int img = blockIdx.x >> 2;
    const int px0 = (blockIdx.x & 3) * 256;

    for (int i = tid; i < 2048; i += 256) {
        int px = i >> 3, chk = i & 7;
        uint32_t sw = (uint32_t)(px * 128 + ((chk ^ (px & 7)) << 4));
        size_t gofs = ((size_t)img * HW + px0 + px) * 64 + chk * 8;
        cp16(sb + PJ_A_HI + sw, ch + gofs);
        cp16(sb + PJ_A_LO + sw, cl + gofs);
    }
    if (tid < 256) {
        int r = tid >> 3, chk = tid & 7;
        uint32_t sw = (uint32_t)(r * 128 + ((chk ^ (r & 7)) << 4));
        cp16(sb + PJ_W_HI + sw, wh + r * 64 + chk * 8);
        cp16(sb + PJ_W_LO + sw, wl + r * 64 + chk * 8);
    }
    CP_COMMIT();
    CP_WAIT0();
    __syncthreads();

    const int wm = wid * 32;
    float acc[2][4][4];
#pragma unroll
    for (int m = 0; m < 2; m++)
#pragma unroll
        for (int n = 0; n < 4; n++)
#pragma unroll
            for (int q = 0; q < 4; q++) acc[m][n][q] = 0.f;

    const int lq = lane >> 2;
    const int lr = lane & 3;

#pragma unroll
    for (int k = 0; k < 4; k++) {
        uint32_t bh[4][2], bl[4][2];
#pragma unroll
        for (int n = 0; n < 4; n++) {
            uint32_t row = n * 8 + lq;
            uint32_t o0 = row * 128 + (((2 * k)     ^ (row & 7)) << 4) + lr * 4;
            uint32_t o1 = row * 128 + (((2 * k + 1) ^ (row & 7)) << 4) + lr * 4;
            bh[n][0] = *(const uint32_t*)(smp + PJ_W_HI + o0);
            bh[n][1] = *(const uint32_t*)(smp + PJ_W_HI + o1);
            bl[n][0] = *(const uint32_t*)(smp + PJ_W_LO + o0);
            bl[n][1] = *(const uint32_t*)(smp + PJ_W_LO + o1);
        }
#pragma unroll
        for (int m = 0; m < 2; m++) {
            uint32_t r0 = wm + m * 16 + lq;
            uint32_t r1 = r0 + 8;
            uint32_t a00 = r0 * 128 + (((2 * k)     ^ (r0 & 7)) << 4) + lr * 4;
            uint32_t a10 = r1 * 128 + (((2 * k)     ^ (r1 & 7)) << 4) + lr * 4;
            uint32_t a01 = r0 * 128 + (((2 * k + 1) ^ (r0 & 7)) << 4) + lr * 4;
            uint32_t a11 = r1 * 128 + (((2 * k + 1) ^ (r1 & 7)) << 4) + lr * 4;
            uint32_t Ah[4], Al[4];
            Ah[0] = *(const uint32_t*)(smp + PJ_A_HI + a00);
            Ah[1] = *(const uint32_t*)(smp + PJ_A_HI + a10);
            Ah[2] = *(const uint32_t*)(smp + PJ_A_HI + a01);
            Ah[3] = *(const uint32_t*)(smp + PJ_A_HI + a11);
            Al[0] = *(const uint32_t*)(smp + PJ_A_LO + a00);
            Al[1] = *(const uint32_t*)(smp + PJ_A_LO + a10);
            Al[2] = *(const uint32_t*)(smp + PJ_A_LO + a01);
            Al[3] = *(const uint32_t*)(smp + PJ_A_LO + a11);
#pragma unroll
            for (int n = 0; n < 4; n++) {
                MMA16816(acc[m][n], Ah[0], Ah[1], Ah[2], Ah[3], bh[n][0], bh[n][1]);
                MMA16816(acc[m][n], Al[0], Al[1], Al[2], Al[3], bh[n][0], bh[n][1]);
                MMA16816(acc[m][n], Ah[0], Ah[1], Ah[2], Ah[3], bl[n][0], bl[n][1]);
            }
        }
    }

    const int b    = img >> 6;
    const int head = (img >> 3) & 7;
    const int t    = img & 7;
#pragma unroll
    for (int n = 0; n < 4; n++) {
        int col = n * 8 + lr * 2;
        float b0 = bc[col], b1 = bc[col + 1];
#pragma unroll
        for (int m = 0; m < 2; m++) {
            int px = px0 + wm + m * 16 + lq;
            size_t row0 = (size_t)b * N_ + t * HW + px;
            size_t row1 = row0 + 8;
            size_t g0 = row0 * C_ + head * 32 + col;
            size_t g1 = row1 * C_ + head * 32 + col;
            uint32_t h0, l0, h1, l1;
            split_bf16x2(acc[m][n][0] + b0, acc[m][n][1] + b1, h0, l0);
            split_bf16x2(acc[m][n][2] + b0, acc[m][n][3] + b1, h1, l1);
            *(uint32_t*)(vhi + g0) = h0;
            *(uint32_t*)(vlo + g0) = l0;
            *(uint32_t*)(vhi + g1) = h1;
            *(uint32_t*)(vlo + g1) = l1;
        }
    }
}

// =================================================================================
extern "C" void kernel_launch(void* const* d_in, const int* in_sizes, int n_in,
                              void* d_out, int out_size)
{
    const float* x      = (const float*)d_in[0];
    const float* w_qk   = (const float*)d_in[1];
    const float* w_corr = (const float*)d_in[2];
    const float* b_corr = (const float*)d_in[3];
    const float* w_proj = (const float*)d_in[4];
    const float* b_proj = (const float*)d_in[5];
    float* out = (float*)d_out;

    __nv_bfloat16 *qhp, *qlp, *khp, *klp, *xhi, *xlo, *vhi, *vlo;
    __nv_bfloat16 *wqh, *wql, *wph, *wpl, *chp, *clp, *wch, *wcl;
    cudaGetSymbolAddress((void**)&qhp, g_qh);
    cudaGetSymbolAddress((void**)&qlp, g_ql);
    cudaGetSymbolAddress((void**)&khp, g_kh);
    cudaGetSymbolAddress((void**)&klp, g_kl);
    cudaGetSymbolAddress((void**)&xhi, g_xhi);
    cudaGetSymbolAddress((void**)&xlo, g_xlo);
    cudaGetSymbolAddress((void**)&vhi, g_vhi);
    cudaGetSymbolAddress((void**)&vlo, g_vlo);
    cudaGetSymbolAddress((void**)&wqh, g_wqk_hi);
    cudaGetSymbolAddress((void**)&wql, g_wqk_lo);
    cudaGetSymbolAddress((void**)&wph, g_wpj_hi);
    cudaGetSymbolAddress((void**)&wpl, g_wpj_lo);
    cudaGetSymbolAddress((void**)&chp, g_ch);
    cudaGetSymbolAddress((void**)&clp, g_cl);
    cudaGetSymbolAddress((void**)&wch, g_wcT_hi);
    cudaGetSymbolAddress((void**)&wcl, g_wcT_lo);

    cudaFuncSetAttribute(gemm_qk,   cudaFuncAttributeMaxDynamicSharedMemorySize, GM_SMEM);
    cudaFuncSetAttribute(gemm_proj, cudaFuncAttributeMaxDynamicSharedMemorySize, GM_SMEM);
    cudaFuncSetAttribute(corr_mma,  cudaFuncAttributeMaxDynamicSharedMemorySize, CM_SMEM);
    cudaFuncSetAttribute(proj_mma,  cudaFuncAttributeMaxDynamicSharedMemorySize, PJ_SMEM);

    // 0) hi/lo splits + w_corr prep
    conv_split<<<(M_TOT * C_ / 4 + 255) / 256, 256>>>((const float4*)x, (uint2*)xhi, (uint2*)xlo, M_TOT * C_ / 4);
    conv_split<<<(512 * 256 / 4 + 255) / 256, 256>>>((const float4*)w_qk, (uint2*)wqh, (uint2*)wql, 512 * 256 / 4);
    conv_split<<<(256 * 256 / 4 + 255) / 256, 256>>>((const float4*)w_proj, (uint2*)wph, (uint2*)wpl, 256 * 256 / 4);
    prep_w<<<8, 256>>>(w_corr, wch, wcl);

    // 1) qk GEMM fused with normalize + temporal shift -> q/k bf16 hi/lo
    gemm_qk<<<dim3(4, 512), 256, GM_SMEM>>>(xhi, xlo, wqh, wql, qhp, qlp, khp, klp);

    // 2) banded tensor-core 7x7 correlation -> corr bf16 hi/lo
    corr_mma<<<BHT * 4, 512, CM_SMEM>>>(qhp, qlp, khp, klp, chp, clp);

    // 3) projection (49->32) via mma -> v bf16 hi/lo
    proj_mma<<<BHT * 4, 256, PJ_SMEM>>>(chp, clp, wch, wcl, b_corr, vhi, vlo);

    // 4) out = v @ w_proj^T + b_proj
    gemm_proj<<<dim3(2, 512), 256, GM_SMEM>>>(vhi, vlo, wph, wpl, b_proj, out, 256);
}

// round 10
// speedup vs baseline: 1.2651x; 1.1558x over previous
#include <cuda_runtime.h>
#include <cuda_bf16.h>
#include <math.h>
#include <stdint.h>

#define B_    8
#define NH    8
#define T_    8
#define HD    32
#define C_    256
#define N_    8192
#define HW    1024
#define BHT   512            // B*NH*T
#define M_TOT 65536          // B*N

// ---------------- scratch (static device globals; no allocation) ----------------
__device__ __nv_bfloat16 g_qh[(size_t)BHT * HW * 32];  // q hi [img][px][ch]
__device__ __nv_bfloat16 g_ql[(size_t)BHT * HW * 32];
__device__ __nv_bfloat16 g_kh[(size_t)BHT * HW * 32];  // k hi (shifted) [img][px][ch]
__device__ __nv_bfloat16 g_kl[(size_t)BHT * HW * 32];
__device__ __nv_bfloat16 g_xhi[(size_t)M_TOT * C_];
__device__ __nv_bfloat16 g_xlo[(size_t)M_TOT * C_];
__device__ __nv_bfloat16 g_vhi[(size_t)M_TOT * C_];
__device__ __nv_bfloat16 g_vlo[(size_t)M_TOT * C_];
__device__ __nv_bfloat16 g_wqk_hi[512 * 256];
__device__ __nv_bfloat16 g_wqk_lo[512 * 256];
__device__ __nv_bfloat16 g_wpj_hi[256 * 256];
__device__ __nv_bfloat16 g_wpj_lo[256 * 256];
__device__ __nv_bfloat16 g_wcT_hi[32 * 64];            // w_corr [e][j'=dy*8+dx] padded
__device__ __nv_bfloat16 g_wcT_lo[32 * 64];

// ======================= asm helpers ==================
__device__ __forceinline__ uint32_t smem_u32(const void* p) {
    uint32_t a;
    asm("{ .reg .u64 t; cvta.to.shared.u64 t, %1; cvt.u32.u64 %0, t; }" : "=r"(a) : "l"(p));
    return a;
}
__device__ __forceinline__ void cp16(uint32_t saddr, const void* g) {
    asm volatile("cp.async.cg.shared.global [%0], [%1], 16;" :: "r"(saddr), "l"(g));
}
#define CP_COMMIT() asm volatile("cp.async.commit_group;" ::: "memory")
#define CP_WAIT1()  asm volatile("cp.async.wait_group 1;" ::: "memory")
#define CP_WAIT0()  asm volatile("cp.async.wait_group 0;" ::: "memory")

#define LDSM4(r0, r1, r2, r3, addr) \
    asm volatile("ldmatrix.sync.aligned.m8n8.x4.shared.b16 {%0,%1,%2,%3}, [%4];" \
                 : "=r"(r0), "=r"(r1), "=r"(r2), "=r"(r3) : "r"(addr))
#define MMA16816(c, a0, a1, a2, a3, b0, b1) \
    asm volatile("mma.sync.aligned.m16n8k16.row.col.f32.bf16.bf16.f32 " \
                 "{%0,%1,%2,%3},{%4,%5,%6,%7},{%8,%9},{%0,%1,%2,%3};" \
                 : "+f"((c)[0]), "+f"((c)[1]), "+f"((c)[2]), "+f"((c)[3]) \
                 : "r"(a0), "r"(a1), "r"(a2), "r"(a3), "r"(b0), "r"(b1))

__device__ __forceinline__ void split_bf16x2(float a, float b, uint32_t& hi, uint32_t& lo) {
    __nv_bfloat162 hb = __floats2bfloat162_rn(a, b);
    float r0 = a - __bfloat162float(__low2bfloat16(hb));
    float r1 = b - __bfloat162float(__high2bfloat16(hb));
    __nv_bfloat162 lb = __floats2bfloat162_rn(r0, r1);
    hi = *(uint32_t*)&hb;
    lo = *(uint32_t*)&lb;
}

// =================================================================================
__global__ void __launch_bounds__(256)
conv_split(const float4* __restrict__ in, uint2* __restrict__ hi,
           uint2* __restrict__ lo, int n4)
{
    int i = blockIdx.x * 256 + threadIdx.x;
    if (i >= n4) return;
    float4 f = in[i];
    uint32_t h0, l0, h1, l1;
    split_bf16x2(f.x, f.y, h0, l0);
    split_bf16x2(f.z, f.w, h1, l1);
    hi[i] = make_uint2(h0, h1);
    lo[i] = make_uint2(l0, l1);
}

// w_corr [32 e][49 j] -> padded [32 e][64 j'] with j' = dy*8+dx
__global__ void __launch_bounds__(256)
prep_w(const float* __restrict__ wc, __nv_bfloat16* __restrict__ wh,
       __nv_bfloat16* __restrict__ wl)
{
    int i = blockIdx.x * 256 + threadIdx.x;
    if (i >= 32 * 64) return;
    int e = i >> 6, jp = i & 63;
    int dy = jp >> 3, dx = jp & 7;
    float v = (dy < 7 && dx < 7) ? wc[e * 49 + dy * 7 + dx] : 0.f;
    __nv_bfloat16 h = __float2bfloat16(v);
    float r = v - __bfloat162float(h);
    wh[i] = h;
    wl[i] = __float2bfloat16(r);
}

// =================================================================================
// Shared GEMM machinery (proven): 128x128 block, 3-stage cp.async, K=256, 3-term.
// =================================================================================
#define KGEMM 256
#define NTILES 8
#define GM_STAGE 32768
#define GM_SMEM  (3 * GM_STAGE)

__device__ __forceinline__ void stage_load(
    uint32_t sbase, const __nv_bfloat16* __restrict__ Ahi,
    const __nv_bfloat16* __restrict__ Alo, const __nv_bfloat16* __restrict__ Bhi,
    const __nv_bfloat16* __restrict__ Blo, int m0, int n0, int kt, int tid)
{
    int t = tid * 2;
    int row = t >> 2;
    int cb  = t & 3;
#pragma unroll
    for (int j = 0; j < 2; j++) {
        int c16 = cb + j;
        uint32_t soff = (uint32_t)(row * 64 + ((c16 ^ ((row >> 1) & 3)) << 4));
        size_t ga = (size_t)row * KGEMM + kt * 32 + c16 * 8;
        cp16(sbase +     0 + soff, Ahi + (size_t)m0 * KGEMM + ga);
        cp16(sbase +  8192 + soff, Alo + (size_t)m0 * KGEMM + ga);
        cp16(sbase + 16384 + soff, Bhi + (size_t)n0 * KGEMM + ga);
        cp16(sbase + 24576 + soff, Blo + (size_t)n0 * KGEMM + ga);
    }
}

__device__ __forceinline__ void gemm_mainloop(
    const __nv_bfloat16* __restrict__ Ahi, const __nv_bfloat16* __restrict__ Alo,
    const __nv_bfloat16* __restrict__ Bhi, const __nv_bfloat16* __restrict__ Blo,
    uint32_t sb, int m0, int n0, int tid, int lane, int wm, int wn,
    float acc[4][4][4])
{
#pragma unroll
    for (int i = 0; i < 4; i++)
#pragma unroll
        for (int j = 0; j < 4; j++)
#pragma unroll
            for (int q = 0; q < 4; q++) acc[i][j][q] = 0.f;

    stage_load(sb,            Ahi, Alo, Bhi, Blo, m0, n0, 0, tid);
    CP_COMMIT();
    stage_load(sb + GM_STAGE, Ahi, Alo, Bhi, Blo, m0, n0, 1, tid);
    CP_COMMIT();

    const uint32_t l2 = lane & 15;
    const uint32_t bsel = (lane & 16) ? 8192u : 0u;

    int stage = 0;
    int lstage = 2;
    for (int kt = 0; kt < NTILES; kt++) {
        CP_WAIT1();
        __syncthreads();
        if (kt + 2 < NTILES)
            stage_load(sb + lstage * GM_STAGE, Ahi, Alo, Bhi, Blo, m0, n0, kt + 2, tid);
        CP_COMMIT();
        lstage = stage;

        const uint32_t sa = sb + stage * GM_STAGE;
        stage = (stage == 2) ? 0 : stage + 1;

#pragma unroll
        for (int ks = 0; ks < 2; ks++) {
            uint32_t aaddr[4], baddr[4];
            {
                uint32_t achk = (uint32_t)(ks * 2) + (lane >> 4);
#pragma unroll
                for (int i = 0; i < 4; i++) {
                    uint32_t r = wm + l2 + i * 16;
                    aaddr[i] = sa + r * 64 + ((achk ^ ((r >> 1) & 3)) << 4);
                }
                uint32_t bchk = (uint32_t)(ks * 2) + ((l2 >> 3) & 1);
#pragma unroll
                for (int j = 0; j < 4; j++) {
                    uint32_t r = wn + (l2 & 7) + j * 8;
                    baddr[j] = sa + 16384 + r * 64 + ((bchk ^ ((r >> 1) & 3)) << 4) + bsel;
                }
            }
            uint32_t a[4][4], al[4][4], b4[4][4];
#pragma unroll
            for (int i = 0; i < 4; i++) LDSM4(a[i][0], a[i][1], a[i][2], a[i][3], aaddr[i]);
#pragma unroll
            for (int j = 0; j < 4; j++) LDSM4(b4[j][0], b4[j][1], b4[j][2], b4[j][3], baddr[j]);
#pragma unroll
            for (int i = 0; i < 4; i++) LDSM4(al[i][0], al[i][1], al[i][2], al[i][3], aaddr[i] + 8192);
#pragma unroll
            for (int i = 0; i < 4; i++)
#pragma unroll
                for (int j = 0; j < 4; j++)
                    MMA16816(acc[i][j], a[i][0], a[i][1], a[i][2], a[i][3], b4[j][0], b4[j][1]);
#pragma unroll
            for (int i = 0; i < 4; i++)
#pragma unroll
                for (int j = 0; j < 4; j++)
                    MMA16816(acc[i][j], a[i][0], a[i][1], a[i][2], a[i][3], b4[j][2], b4[j][3]);
#pragma unroll
            for (int i = 0; i < 4; i++)
#pragma unroll
                for (int j = 0; j < 4; j++)
                    MMA16816(acc[i][j], al[i][0], al[i][1], al[i][2], al[i][3], b4[j][0], b4[j][1]);
        }
    }
}

// =================================================================================
// GEMM1 fused: qk GEMM + L2-normalize + temporal shift; emits q AND k as
// bf16 hi/lo in identical [img][px][ch] layout.
// =================================================================================
__global__ void __launch_bounds__(256, 2)
gemm_qk(const __nv_bfloat16* __restrict__ Ahi, const __nv_bfloat16* __restrict__ Alo,
        const __nv_bfloat16* __restrict__ Bhi, const __nv_bfloat16* __restrict__ Blo,
        __nv_bfloat16* __restrict__ qh, __nv_bfloat16* __restrict__ ql,
        __nv_bfloat16* __restrict__ kh, __nv_bfloat16* __restrict__ kl)
{
    const bool is_k = (blockIdx.x >= 2);
    const int tt_blk = (blockIdx.y >> 3) & 7;
    if (is_k && tt_blk == 0) return;        // dead k tile (shifted away)

    extern __shared__ char smg[];
    const uint32_t sb = smem_u32(smg);
    const int tid = threadIdx.x;
    const int lane = tid & 31;
    const int wid = tid >> 5;
    const int m0 = blockIdx.y * 128;
    const int n0 = blockIdx.x * 128;
    const int wm = (wid >> 2) * 64;
    const int wn = (wid & 3) * 32;

    float acc[4][4][4];
    gemm_mainloop(Ahi, Alo, Bhi, Blo, sb, m0, n0, tid, lane, wm, wn, acc);

    const int head = (((n0 & 255) + wn) >> 5);

#pragma unroll
    for (int i = 0; i < 4; i++) {
#pragma unroll
        for (int h = 0; h < 2; h++) {
            float v0[4], v1[4];
            float ss = 0.f;
#pragma unroll
            for (int j = 0; j < 4; j++) {
                v0[j] = acc[i][j][2 * h];
                v1[j] = acc[i][j][2 * h + 1];
                ss += v0[j] * v0[j] + v1[j] * v1[j];
            }
            ss += __shfl_xor_sync(0xffffffffu, ss, 1);
            ss += __shfl_xor_sync(0xffffffffu, ss, 2);
            float inv = 1.0f / fmaxf(sqrtf(ss), 1e-12f);

            int r = m0 + wm + i * 16 + (lane >> 2) + h * 8;
            int b  = r >> 13;
            int tt = (r >> 10) & 7;
            int p  = r & 1023;

            uint32_t hw[4], lw[4];
#pragma unroll
            for (int j = 0; j < 4; j++)
                split_bf16x2(v0[j] * inv, v1[j] * inv, hw[j], lw[j]);

            if (!is_k) {
                size_t base = ((size_t)(b * 64 + head * 8 + tt) * HW + p) * 32;
#pragma unroll
                for (int j = 0; j < 4; j++) {
                    int col = j * 8 + (lane & 3) * 2;
                    *(uint32_t*)(qh + base + col) = hw[j];
                    *(uint32_t*)(ql + base + col) = lw[j];
                }
            } else {
                if (tt >= 1) {
                    size_t base = ((size_t)(b * 64 + head * 8 + (tt - 1)) * HW + p) * 32;
#pragma unroll
                    for (int j = 0; j < 4; j++) {
                        int col = j * 8 + (lane & 3) * 2;
                        *(uint32_t*)(kh + base + col) = hw[j];
                        *(uint32_t*)(kl + base + col) = lw[j];
                    }
                }
                if (tt == 7) {
                    size_t base = ((size_t)(b * 64 + head * 8 + 7) * HW + p) * 32;
#pragma unroll
                    for (int j = 0; j < 4; j++) {
                        int col = j * 8 + (lane & 3) * 2;
                        *(uint32_t*)(kh + base + col) = hw[j];
                        *(uint32_t*)(kl + base + col) = lw[j];
                    }
                }
            }
        }
    }
}

// =================================================================================
// GEMM4: out = v @ w_proj^T + bias, fp32 out
// =================================================================================
__global__ void __launch_bounds__(256, 2)
gemm_proj(const __nv_bfloat16* __restrict__ Ahi, const __nv_bfloat16* __restrict__ Alo,
          const __nv_bfloat16* __restrict__ Bhi, const __nv_bfloat16* __restrict__ Blo,
          const float* __restrict__ bias, float* __restrict__ C, int ldc)
{
    extern __shared__ char smg[];
    const uint32_t sb = smem_u32(smg);
    const int tid = threadIdx.x;
    const int lane = tid & 31;
    const int wid = tid >> 5;
    const int m0 = blockIdx.y * 128;
    const int n0 = blockIdx.x * 128;
    const int wm = (wid >> 2) * 64;
    const int wn = (wid & 3) * 32;

    float acc[4][4][4];
    gemm_mainloop(Ahi, Alo, Bhi, Blo, sb, m0, n0, tid, lane, wm, wn, acc);

#pragma unroll
    for (int j = 0; j < 4; j++) {
        int c = n0 + wn + j * 8 + (lane & 3) * 2;
        float b0 = bias[c], b1 = bias[c + 1];
#pragma unroll
        for (int i = 0; i < 4; i++) {
            int r = m0 + wm + i * 16 + (lane >> 2);
            *(float2*)(C + (size_t)r * ldc + c) =
                make_float2(acc[i][j][0] + b0, acc[i][j][1] + b1);
            *(float2*)(C + (size_t)(r + 8) * ldc + c) =
                make_float2(acc[i][j][2] + b0, acc[i][j][3] + b1);
        }
    }
}

// =================================================================================
// corr_proj: banded tensor-core 7x7 correlation FUSED with (49->32) projection.
// Block = quarter image, 512 thr (16 warps), warp = one 16-px segment.
// Phase 1 (per dy): corr band via mma -> per-warp smem corr buffer (bf16 hi/lo).
// Phase 2: proj m16n32k64 3-term mma against w_corr in smem -> v hi/lo gmem.
// smem map:
//   q hi 0 / lo 16384 (16KB each)
//   k hi 32768 / lo 68608 (35840 each; 14 rows x 40 px, 64B/row, swizzled)
//   w hi 104448 / lo 108544 (4KB each; 32 rows x 128B, swizzled)
//   corr buf 112640 + w*4096 (per warp: hi 2KB + lo 2KB; 16 rows x 128B, swizzled)
//   sbuf 178176 + w*1664 (per warp fp32 staging)
// total 204800
// =================================================================================
#define CPK_KH 32768
#define CPK_KL 68608
#define CPK_WH 104448
#define CPK_WL 108544
#define CPK_CS 112640
#define CPK_SB 178176
#define CPK_SMEM 204800

__global__ void __launch_bounds__(512)
corr_proj(const __nv_bfloat16* __restrict__ qh, const __nv_bfloat16* __restrict__ ql,
          const __nv_bfloat16* __restrict__ kh, const __nv_bfloat16* __restrict__ kl,
          const __nv_bfloat16* __restrict__ wch, const __nv_bfloat16* __restrict__ wcl,
          const float* __restrict__ bc,
          __nv_bfloat16* __restrict__ vhi, __nv_bfloat16* __restrict__ vlo)
{
    extern __shared__ char sm[];
    const uint32_t sb = smem_u32(sm);
    const int tid  = threadIdx.x;
    const int lane = tid & 31;
    const int w    = tid >> 5;           // warp = segment 0..15
    const int img  = blockIdx.x >> 2;
    const int yq   = (blockIdx.x & 3) * 8;

    // zero whole k region (hi+lo: 71680 B = 4480 uint4)
    for (int i = tid; i < 4480; i += 512)
        ((uint4*)(sm + CPK_KH))[i] = make_uint4(0, 0, 0, 0);
    __syncthreads();

    // q fill: 256 px x 4 chunks x {hi,lo} = 2048 cp16
    for (int i = tid; i < 2048; i += 512) {
        int hl = i >> 10;
        int px = (i >> 2) & 255;
        int c  = i & 3;
        const __nv_bfloat16* src = (hl ? ql : qh) +
            ((size_t)img * HW + yq * 32 + px) * 32 + c * 8;
        uint32_t dst = sb + hl * 16384 + px * 64 + ((c ^ ((px >> 1) & 3)) << 4);
        cp16(dst, src);
    }
    // k fill: 14 rows x 32 px x 4 chunks x {hi,lo} = 3584 cp16 (valid rows only)
    for (int i = tid; i < 3584; i += 512) {
        int hl = i & 1;
        int j  = i >> 1;
        int row = j >> 7;
        int r2  = j & 127;
        int px  = r2 >> 2;
        int c   = r2 & 3;
        int y = yq - 3 + row;
        if (y >= 0 && y < 32) {
            int rlin = row * 40 + px + 3;
            uint32_t dst = sb + CPK_KH + hl * 35840 + rlin * 64 +
                           ((c ^ ((rlin >> 1) & 3)) << 4);
            const __nv_bfloat16* src = (hl ? kl : kh) +
                ((size_t)img * HW + y * 32 + px) * 32 + c * 8;
            cp16(dst, src);
        }
    }
    // w fill: 32 rows x 8 chunks x {hi,lo} = 512 cp16 (one per thread)
    {
        int hl  = tid >> 8;
        int r   = (tid >> 3) & 31;
        int chk = tid & 7;
        uint32_t dst = sb + (hl ? CPK_WL : CPK_WH) + r * 128 + ((chk ^ (r & 7)) << 4);
        cp16(dst, (hl ? wcl : wch) + r * 64 + chk * 8);
    }
    CP_COMMIT();
    CP_WAIT0();
    __syncthreads();

    const int yloc = w >> 1;
    const int x0   = (w & 1) * 16;

    // A fragments (q, reused across all dy): 2 k16 chunks, hi+lo
    uint32_t Ah[2][4], Al[2][4];
#pragma unroll
    for (int f = 0; f < 2; f++) {
        uint32_t r = w * 16 + (lane & 15);
        uint32_t c = f * 2 + (lane >> 4);
        uint32_t addr = sb + r * 64 + ((c ^ ((r >> 1) & 3)) << 4);
        LDSM4(Ah[f][0], Ah[f][1], Ah[f][2], Ah[f][3], addr);
        LDSM4(Al[f][0], Al[f][1], Al[f][2], Al[f][3], addr + 16384);
    }

    float* sbuf = (float*)(sm + CPK_SB + w * 1664);   // [16][26], band-read stride 27
    const uint32_t cs_hi = CPK_CS + w * 4096;         // char offsets into sm
    const uint32_t cs_lo = cs_hi + 2048;
    const int lq = lane >> 2, lr = lane & 3;
    const int rr = lane >> 1;                          // band row 0..15
    const int odd = lane & 1;

#pragma unroll 1
    for (int dy = 0; dy < 7; dy++) {
        const int row = yloc + dy;
        uint32_t Bh[3][4], Bl[3][4];
#pragma unroll
        for (int nt = 0; nt < 3; nt++) {
            uint32_t rlin = row * 40 + x0 + nt * 8 + (lane & 7);
            uint32_t c = lane >> 3;
            uint32_t addr = sb + CPK_KH + rlin * 64 + ((c ^ ((rlin >> 1) & 3)) << 4);
            LDSM4(Bh[nt][0], Bh[nt][1], Bh[nt][2], Bh[nt][3], addr);
            LDSM4(Bl[nt][0], Bl[nt][1], Bl[nt][2], Bl[nt][3], addr + 35840);
        }
        float acc[3][4];
#pragma unroll
        for (int nt = 0; nt < 3; nt++)
#pragma unroll
            for (int q = 0; q < 4; q++) acc[nt][q] = 0.f;

#pragma unroll
        for (int nt = 0; nt < 3; nt++) {
            MMA16816(acc[nt], Ah[0][0], Ah[0][1], Ah[0][2], Ah[0][3], Bh[nt][0], Bh[nt][1]);
            MMA16816(acc[nt], Ah[1][0], Ah[1][1], Ah[1][2], Ah[1][3], Bh[nt][2], Bh[nt][3]);
            MMA16816(acc[nt], Ah[0][0], Ah[0][1], Ah[0][2], Ah[0][3], Bl[nt][0], Bl[nt][1]);
            MMA16816(acc[nt], Ah[1][0], Ah[1][1], Ah[1][2], Ah[1][3], Bl[nt][2], Bl[nt][3]);
            MMA16816(acc[nt], Al[0][0], Al[0][1], Al[0][2], Al[0][3], Bh[nt][0], Bh[nt][1]);
            MMA16816(acc[nt], Al[1][0], Al[1][1], Al[1][2], Al[1][3], Bh[nt][2], Bh[nt][3]);
        }

        // stage accums to per-warp fp32 buffer
        __syncwarp();
#pragma unroll
        for (int nt = 0; nt < 3; nt++) {
            *(float2*)&sbuf[lq * 26 + nt * 8 + lr * 2]       = make_float2(acc[nt][0], acc[nt][1]);
            *(float2*)&sbuf[(lq + 8) * 26 + nt * 8 + lr * 2] = make_float2(acc[nt][2], acc[nt][3]);
        }
        __syncwarp();

        // band extract row rr (cols rr..rr+6 == stride-27 read) -> smem corr buf
        {
            uint32_t coff = rr * 128 + ((dy ^ (rr & 7)) << 4) + odd * 8;
            if (!odd) {
                float s0 = sbuf[27 * rr + 0], s1 = sbuf[27 * rr + 1];
                float s2 = sbuf[27 * rr + 2], s3 = sbuf[27 * rr + 3];
                uint32_t h0, l0, h1, l1;
                split_bf16x2(s0, s1, h0, l0);
                split_bf16x2(s2, s3, h1, l1);
                *(uint2*)(sm + cs_hi + coff) = make_uint2(h0, h1);
                *(uint2*)(sm + cs_lo + coff) = make_uint2(l0, l1);
            } else {
                float s4 = sbuf[27 * rr + 4], s5 = sbuf[27 * rr + 5];
                float s6 = sbuf[27 * rr + 6];
                uint32_t h0, l0, h1, l1;
                split_bf16x2(s4, s5, h0, l0);
                split_bf16x2(s6, 0.f, h1, l1);
                *(uint2*)(sm + cs_hi + coff) = make_uint2(h0, h1);
                *(uint2*)(sm + cs_lo + coff) = make_uint2(l0, l1);
            }
        }
        __syncwarp();
    }

    // zero tail chunk j' = 56..63
    {
        uint32_t coff = rr * 128 + ((7 ^ (rr & 7)) << 4) + odd * 8;
        uint2 z = make_uint2(0, 0);
        *(uint2*)(sm + cs_hi + coff) = z;
        *(uint2*)(sm + cs_lo + coff) = z;
    }
    __syncwarp();

    // ---------- Phase 2: projection m16 x n32 x k64, 3-term ----------
    float pacc[4][4];
#pragma unroll
    for (int n = 0; n < 4; n++)
#pragma unroll
        for (int q = 0; q < 4; q++) pacc[n][q] = 0.f;

#pragma unroll
    for (int k = 0; k < 4; k++) {
        uint32_t bh[4][2], bl[4][2];
#pragma unroll
        for (int n = 0; n < 4; n++) {
            uint32_t wr = n * 8 + lq;
            uint32_t o0 = wr * 128 + (((2 * k)     ^ (wr & 7)) << 4) + lr * 4;
            uint32_t o1 = wr * 128 + (((2 * k + 1) ^ (wr & 7)) << 4) + lr * 4;
            bh[n][0] = *(const uint32_t*)(sm + CPK_WH + o0);
            bh[n][1] = *(const uint32_t*)(sm + CPK_WH + o1);
            bl[n][0] = *(const uint32_t*)(sm + CPK_WL + o0);
            bl[n][1] = *(const uint32_t*)(sm + CPK_WL + o1);
        }
        uint32_t r0 = lq, r1 = lq + 8;
        uint32_t a00 = r0 * 128 + (((2 * k)     ^ (r0 & 7)) << 4) + lr * 4;
        uint32_t a10 = r1 * 128 + (((2 * k)     ^ (r1 & 7)) << 4) + lr * 4;
        uint32_t a01 = r0 * 128 + (((2 * k + 1) ^ (r0 & 7)) << 4) + lr * 4;
        uint32_t a11 = r1 * 128 + (((2 * k + 1) ^ (r1 & 7)) << 4) + lr * 4;
        uint32_t Pa[4], Pl[4];
        Pa[0] = *(const uint32_t*)(sm + cs_hi + a00);
        Pa[1] = *(const uint32_t*)(sm + cs_hi + a10);
        Pa[2] = *(const uint32_t*)(sm + cs_hi + a01);
        Pa[3] = *(const uint32_t*)(sm + cs_hi + a11);
        Pl[0] = *(const uint32_t*)(sm + cs_lo + a00);
        Pl[1] = *(const uint32_t*)(sm + cs_lo + a10);
        Pl[2] = *(const uint32_t*)(sm + cs_lo + a01);
        Pl[3] = *(const uint32_t*)(sm + cs_lo + a11);
#pragma unroll
        for (int n = 0; n < 4; n++) {
            MMA16816(pacc[n], Pa[0], Pa[1], Pa[2], Pa[3], bh[n][0], bh[n][1]);
            MMA16816(pacc[n], Pl[0], Pl[1], Pl[2], Pl[3], bh[n][0], bh[n][1]);
            MMA16816(pacc[n], Pa[0], Pa[1], Pa[2], Pa[3], bl[n][0], bl[n][1]);
        }
    }

    // epilogue: v + b_corr, split hi/lo, store
    const int b    = img >> 6;
    const int head = (img >> 3) & 7;
    const int t    = img & 7;
    const int y    = yq + yloc;
    const int p0   = y * 32 + x0 + lq;      // pixel for acc rows {0..7}
#pragma unroll
    for (int n = 0; n < 4; n++) {
        int col = n * 8 + lr * 2;
        float b0 = bc[col], b1 = bc[col + 1];
        size_t row0 = (size_t)b * N_ + t * HW + p0;
        size_t g0 = row0 * C_ + head * 32 + col;
        size_t g1 = (row0 + 8) * C_ + head * 32 + col;
        uint32_t h0, l0, h1, l1;
        split_bf16x2(pacc[n][0] + b0, pacc[n][1] + b1, h0, l0);
        split_bf16x2(pacc[n][2] + b0, pacc[n][3] + b1, h1, l1);
        *(uint32_t*)(vhi + g0) = h0;
        *(uint32_t*)(vlo + g0) = l0;
        *(uint32_t*)(vhi + g1) = h1;
        *(uint32_t*)(vlo + g1) = l1;
    }
}

// =================================================================================
extern "C" void kernel_launch(void* const* d_in, const int* in_sizes, int n_in,
                              void* d_out, int out_size)
{
    const float* x      = (const float*)d_in[0];
    const float* w_qk   = (const float*)d_in[1];
    const float* w_corr = (const float*)d_in[2];
    const float* b_corr = (const float*)d_in[3];
    const float* w_proj = (const float*)d_in[4];
    const float* b_proj = (const float*)d_in[5];
    float* out = (float*)d_out;

    __nv_bfloat16 *qhp, *qlp, *khp, *klp, *xhi, *xlo, *vhi, *vlo;
    __nv_bfloat16 *wqh, *wql, *wph, *wpl, *wch, *wcl;
    cudaGetSymbolAddress((void**)&qhp, g_qh);
    cudaGetSymbolAddress((void**)&qlp, g_ql);
    cudaGetSymbolAddress((void**)&khp, g_kh);
    cudaGetSymbolAddress((void**)&klp, g_kl);
    cudaGetSymbolAddress((void**)&xhi, g_xhi);
    cudaGetSymbolAddress((void**)&xlo, g_xlo);
    cudaGetSymbolAddress((void**)&vhi, g_vhi);
    cudaGetSymbolAddress((void**)&vlo, g_vlo);
    cudaGetSymbolAddress((void**)&wqh, g_wqk_hi);
    cudaGetSymbolAddress((void**)&wql, g_wqk_lo);
    cudaGetSymbolAddress((void**)&wph, g_wpj_hi);
    cudaGetSymbolAddress((void**)&wpl, g_wpj_lo);
    cudaGetSymbolAddress((void**)&wch, g_wcT_hi);
    cudaGetSymbolAddress((void**)&wcl, g_wcT_lo);

    cudaFuncSetAttribute(gemm_qk,   cudaFuncAttributeMaxDynamicSharedMemorySize, GM_SMEM);
    cudaFuncSetAttribute(gemm_proj, cudaFuncAttributeMaxDynamicSharedMemorySize, GM_SMEM);
    cudaFuncSetAttribute(corr_proj, cudaFuncAttributeMaxDynamicSharedMemorySize, CPK_SMEM);

    // 0) hi/lo splits + w_corr prep
    conv_split<<<(M_TOT * C_ / 4 + 255) / 256, 256>>>((const float4*)x, (uint2*)xhi, (uint2*)xlo, M_TOT * C_ / 4);
    conv_split<<<(512 * 256 / 4 + 255) / 256, 256>>>((const float4*)w_qk, (uint2*)wqh, (uint2*)wql, 512 * 256 / 4);
    conv_split<<<(256 * 256 / 4 + 255) / 256, 256>>>((const float4*)w_proj, (uint2*)wph, (uint2*)wpl, 256 * 256 / 4);
    prep_w<<<8, 256>>>(w_corr, wch, wcl);

    // 1) qk GEMM fused with normalize + temporal shift -> q/k bf16 hi/lo
    gemm_qk<<<dim3(4, 512), 256, GM_SMEM>>>(xhi, xlo, wqh, wql, qhp, qlp, khp, klp);

    // 2) fused banded tensor-core correlation + projection -> v bf16 hi/lo
    corr_proj<<<BHT * 4, 512, CPK_SMEM>>>(qhp, qlp, khp, klp, wch, wcl, b_corr, vhi, vlo);

    // 3) out = v @ w_proj^T + b_proj
    gemm_proj<<<dim3(2, 512), 256, GM_SMEM>>>(vhi, vlo, wph, wpl, b_proj, out, 256);
}